// round 1
// baseline (speedup 1.0000x reference)
#include <cuda_runtime.h>
#include <math.h>

// ---------------- problem constants ----------------
#define NB     2
#define DIM    2048
#define SEQ    128
#define ALEN   1536
#define TLEN   512
#define HQN    16
#define HKVN   4
#define HDN    128
#define HCN    16
#define HDCN   128
#define FFN    8192
#define NLAYER 2
#define GRP    (HQN / HKVN)   // 4
#define NEGV   (-30000.0f)
#define EPSV   (1e-5f)

// ---------------- device scratch (static, no allocation) ----------------
__device__ float g_x[NB * DIM * SEQ];
__device__ float g_h[NB * DIM * SEQ];
__device__ float g_q[NB * HQN * HDN * SEQ];
__device__ float g_k[NB * HKVN * HDN * SEQ];
__device__ float g_v[NB * HKVN * HDN * SEQ];
__device__ float g_key[NB * HKVN * ALEN * HDN];
__device__ float g_val[NB * HKVN * HDN * ALEN];
__device__ float g_scores[NB * HQN * ALEN * SEQ];
__device__ float g_attn[NB * HQN * HDN * SEQ];
__device__ float g_cscores[NB * HCN * TLEN * SEQ];
__device__ float g_gate[NB * FFN * SEQ];
__device__ float g_up[NB * FFN * SEQ];

// ---------------- elementwise copy ----------------
__global__ void copy_kernel(const float* __restrict__ src, float* __restrict__ dst, int n) {
    int i = blockIdx.x * blockDim.x + threadIdx.x;
    if (i < n) dst[i] = src[i];
}

// ---------------- RMSNorm over D for each (b, s); s-major coalesced ----------------
// grid: (SEQ/32, NB), block: (32, 8)
__global__ void rmsnorm_kernel(const float* __restrict__ x, const float* __restrict__ w,
                               float* __restrict__ out) {
    int s = blockIdx.x * 32 + threadIdx.x;
    int b = blockIdx.y;
    const float* xb = x + (long)b * DIM * SEQ;
    float* ob = out + (long)b * DIM * SEQ;
    float ss = 0.0f;
    for (int d = threadIdx.y; d < DIM; d += 8) {
        float v = xb[d * SEQ + s];
        ss += v * v;
    }
    __shared__ float red[8][33];
    red[threadIdx.y][threadIdx.x] = ss;
    __syncthreads();
    if (threadIdx.y == 0) {
        float tot = 0.0f;
        #pragma unroll
        for (int i = 0; i < 8; i++) tot += red[i][threadIdx.x];
        red[0][threadIdx.x] = rsqrtf(tot / (float)DIM + EPSV);
    }
    __syncthreads();
    float inv = red[0][threadIdx.x];
    for (int d = threadIdx.y; d < DIM; d += 8) {
        ob[d * SEQ + s] = xb[d * SEQ + s] * inv * w[d];
    }
}

// ---------------- GEMM TN: C[m,n] (+)= sum_k A[k*M+m] * B[k*N+n] ----------------
// A: weights (K x M row-major). B batched with strideB, C batched with strideC.
// grid: (M/64, N/64, batch), block: (16,16)
__global__ __launch_bounds__(256) void gemm_tn(
    const float* __restrict__ A, const float* __restrict__ Bm, float* __restrict__ C,
    int K, int M, int N, long strideB, long strideC, int accum) {
    __shared__ float As[16][65];
    __shared__ float Bs[16][64];
    const float* Bb = Bm + (long)blockIdx.z * strideB;
    float* Cb = C + (long)blockIdx.z * strideC;
    int bm = blockIdx.x * 64, bn = blockIdx.y * 64;
    int tx = threadIdx.x, ty = threadIdx.y;
    int tid = ty * 16 + tx;
    float acc[4][4] = {{0.f,0.f,0.f,0.f},{0.f,0.f,0.f,0.f},{0.f,0.f,0.f,0.f},{0.f,0.f,0.f,0.f}};
    for (int k0 = 0; k0 < K; k0 += 16) {
        #pragma unroll
        for (int i = 0; i < 4; i++) {
            int t = tid + i * 256;
            int kk = t >> 6, mm = t & 63;
            As[kk][mm] = A[(long)(k0 + kk) * M + bm + mm];
            Bs[kk][mm] = Bb[(long)(k0 + kk) * N + bn + mm];
        }
        __syncthreads();
        #pragma unroll
        for (int kk = 0; kk < 16; kk++) {
            float4 bb = *reinterpret_cast<const float4*>(&Bs[kk][tx * 4]);
            float a0 = As[kk][ty * 4 + 0];
            float a1 = As[kk][ty * 4 + 1];
            float a2 = As[kk][ty * 4 + 2];
            float a3 = As[kk][ty * 4 + 3];
            acc[0][0] += a0 * bb.x; acc[0][1] += a0 * bb.y; acc[0][2] += a0 * bb.z; acc[0][3] += a0 * bb.w;
            acc[1][0] += a1 * bb.x; acc[1][1] += a1 * bb.y; acc[1][2] += a1 * bb.z; acc[1][3] += a1 * bb.w;
            acc[2][0] += a2 * bb.x; acc[2][1] += a2 * bb.y; acc[2][2] += a2 * bb.z; acc[2][3] += a2 * bb.w;
            acc[3][0] += a3 * bb.x; acc[3][1] += a3 * bb.y; acc[3][2] += a3 * bb.z; acc[3][3] += a3 * bb.w;
        }
        __syncthreads();
    }
    #pragma unroll
    for (int i = 0; i < 4; i++) {
        long m = bm + ty * 4 + i;
        #pragma unroll
        for (int j = 0; j < 4; j++) {
            long idx = m * N + bn + tx * 4 + j;
            Cb[idx] = accum ? (Cb[idx] + acc[i][j]) : acc[i][j];
        }
    }
}

// ---------------- GEMM NN: C[m,n] = sum_k A[m*K+k] * B[k*N+n] ----------------
// A batched with (batch / aDiv) * strideA, B/C with strideB/strideC.
// grid: (M/64, N/64, batch), block: (16,16)
__global__ __launch_bounds__(256) void gemm_nn(
    const float* __restrict__ A, const float* __restrict__ Bm, float* __restrict__ C,
    int K, int M, int N, long strideA, int aDiv, long strideB, long strideC) {
    __shared__ float As[16][65];
    __shared__ float Bs[16][64];
    const float* Ab = A + (long)(blockIdx.z / aDiv) * strideA;
    const float* Bb = Bm + (long)blockIdx.z * strideB;
    float* Cb = C + (long)blockIdx.z * strideC;
    int bm = blockIdx.x * 64, bn = blockIdx.y * 64;
    int tx = threadIdx.x, ty = threadIdx.y;
    int tid = ty * 16 + tx;
    float acc[4][4] = {{0.f,0.f,0.f,0.f},{0.f,0.f,0.f,0.f},{0.f,0.f,0.f,0.f},{0.f,0.f,0.f,0.f}};
    for (int k0 = 0; k0 < K; k0 += 16) {
        #pragma unroll
        for (int i = 0; i < 4; i++) {
            int t = tid + i * 256;
            int mm = t >> 4, kk = t & 15;
            As[kk][mm] = Ab[(long)(bm + mm) * K + k0 + kk];
            int kk2 = t >> 6, nn = t & 63;
            Bs[kk2][nn] = Bb[(long)(k0 + kk2) * N + bn + nn];
        }
        __syncthreads();
        #pragma unroll
        for (int kk = 0; kk < 16; kk++) {
            float4 bb = *reinterpret_cast<const float4*>(&Bs[kk][tx * 4]);
            float a0 = As[kk][ty * 4 + 0];
            float a1 = As[kk][ty * 4 + 1];
            float a2 = As[kk][ty * 4 + 2];
            float a3 = As[kk][ty * 4 + 3];
            acc[0][0] += a0 * bb.x; acc[0][1] += a0 * bb.y; acc[0][2] += a0 * bb.z; acc[0][3] += a0 * bb.w;
            acc[1][0] += a1 * bb.x; acc[1][1] += a1 * bb.y; acc[1][2] += a1 * bb.z; acc[1][3] += a1 * bb.w;
            acc[2][0] += a2 * bb.x; acc[2][1] += a2 * bb.y; acc[2][2] += a2 * bb.z; acc[2][3] += a2 * bb.w;
            acc[3][0] += a3 * bb.x; acc[3][1] += a3 * bb.y; acc[3][2] += a3 * bb.z; acc[3][3] += a3 * bb.w;
        }
        __syncthreads();
    }
    #pragma unroll
    for (int i = 0; i < 4; i++) {
        long m = bm + ty * 4 + i;
        #pragma unroll
        for (int j = 0; j < 4; j++) {
            Cb[m * N + bn + tx * 4 + j] = acc[i][j];
        }
    }
}

// ---------------- RoPE in-place on (B, H, 128, S) buffer ----------------
__global__ void rope_kernel(float* __restrict__ q, const int* __restrict__ positions, int H) {
    int idx = blockIdx.x * blockDim.x + threadIdx.x;
    int total = NB * H * 64 * SEQ;
    if (idx >= total) return;
    int s = idx % SEQ;
    int i = (idx / SEQ) % 64;
    int h = (idx / (SEQ * 64)) % H;
    int b = idx / (SEQ * 64 * H);
    float pos = (float)positions[b * SEQ + s];
    float inv = powf(10000.0f, -(float)i / 64.0f);
    float sn, cs;
    sincosf(pos * inv, &sn, &cs);
    long base = (((long)b * H + h) * HDN) * SEQ;
    float x1 = q[base + (long)i * SEQ + s];
    float x2 = q[base + (long)(i + 64) * SEQ + s];
    q[base + (long)i * SEQ + s] = x1 * cs - x2 * sn;
    q[base + (long)(i + 64) * SEQ + s] = x2 * cs + x1 * sn;
}

// ---------------- merge k into key scratch: key[b,k,a,d] ----------------
__global__ void update_key(const float* __restrict__ kc, const float* __restrict__ knew,
                           float* __restrict__ keybuf, const int* __restrict__ wptr) {
    int idx = blockIdx.x * blockDim.x + threadIdx.x;
    const int total = NB * HKVN * ALEN * HDN;
    if (idx >= total) return;
    int w = wptr[0];
    int d = idx % HDN;
    int a = (idx / HDN) % ALEN;
    int kh = (idx / (HDN * ALEN)) % HKVN;
    int b = idx / (HDN * ALEN * HKVN);
    float v;
    if (a >= w && a < w + SEQ) {
        // knew layout (B, HKV, HD, S); cache stores transposed (a, d)
        v = knew[(((long)b * HKVN + kh) * HDN + d) * SEQ + (a - w)];
    } else {
        v = kc[idx];
    }
    keybuf[idx] = v;
}

// ---------------- merge v into val scratch: val[b,k,d,a] ----------------
__global__ void update_val(const float* __restrict__ vc, const float* __restrict__ vnew,
                           float* __restrict__ valbuf, const int* __restrict__ wptr) {
    int idx = blockIdx.x * blockDim.x + threadIdx.x;
    const int total = NB * HKVN * HDN * ALEN;
    if (idx >= total) return;
    int w = wptr[0];
    int a = idx % ALEN;
    int d = (idx / ALEN) % HDN;
    int kh = (idx / (ALEN * HDN)) % HKVN;
    int b = idx / (ALEN * HDN * HKVN);
    float v;
    if (a >= w && a < w + SEQ) {
        v = vnew[(((long)b * HKVN + kh) * HDN + d) * SEQ + (a - w)];
    } else {
        v = vc[idx];
    }
    valbuf[idx] = v;
}

// ---------------- self-attn softmax over a (causal mask from kv_write_index) ----------------
// grid: (SEQ/32, NB*HQN), block (32,8); scores layout [z][a][s]
__global__ void sa_softmax(float* __restrict__ sc, const int* __restrict__ wptr, float scale) {
    int s = blockIdx.x * 32 + threadIdx.x;
    int z = blockIdx.y;
    int w = wptr[0];
    float* p = sc + (long)z * ALEN * SEQ;
    __shared__ float red[8][33];

    float mx = -3.0e38f;
    for (int a = threadIdx.y; a < ALEN; a += 8) {
        float v = p[(long)a * SEQ + s] * scale;
        if (a > w + s) v += NEGV;
        p[(long)a * SEQ + s] = v;
        mx = fmaxf(mx, v);
    }
    red[threadIdx.y][threadIdx.x] = mx;
    __syncthreads();
    if (threadIdx.y == 0) {
        float m = red[0][threadIdx.x];
        #pragma unroll
        for (int i = 1; i < 8; i++) m = fmaxf(m, red[i][threadIdx.x]);
        red[0][threadIdx.x] = m;
    }
    __syncthreads();
    mx = red[0][threadIdx.x];
    __syncthreads();

    float sum = 0.0f;
    for (int a = threadIdx.y; a < ALEN; a += 8) {
        float e = expf(p[(long)a * SEQ + s] - mx);
        p[(long)a * SEQ + s] = e;
        sum += e;
    }
    red[threadIdx.y][threadIdx.x] = sum;
    __syncthreads();
    if (threadIdx.y == 0) {
        float t = red[0][threadIdx.x];
        #pragma unroll
        for (int i = 1; i < 8; i++) t += red[i][threadIdx.x];
        red[0][threadIdx.x] = 1.0f / t;
    }
    __syncthreads();
    float rinv = red[0][threadIdx.x];
    for (int a = threadIdx.y; a < ALEN; a += 8) {
        p[(long)a * SEQ + s] *= rinv;
    }
}

// ---------------- cross-attn softmax over t (length mask from encoder_lengths) ----------------
// grid: (SEQ/32, NB*HCN), block (32,8); scores layout [z][t][s]
__global__ void ca_softmax(float* __restrict__ sc, const int* __restrict__ enc, float scale) {
    int s = blockIdx.x * 32 + threadIdx.x;
    int z = blockIdx.y;
    int b = z / HCN;
    int len = enc[b];
    float* p = sc + (long)z * TLEN * SEQ;
    __shared__ float red[8][33];

    float mx = -3.0e38f;
    for (int t = threadIdx.y; t < TLEN; t += 8) {
        float v = p[(long)t * SEQ + s] * scale;
        if (t >= len) v += NEGV;
        p[(long)t * SEQ + s] = v;
        mx = fmaxf(mx, v);
    }
    red[threadIdx.y][threadIdx.x] = mx;
    __syncthreads();
    if (threadIdx.y == 0) {
        float m = red[0][threadIdx.x];
        #pragma unroll
        for (int i = 1; i < 8; i++) m = fmaxf(m, red[i][threadIdx.x]);
        red[0][threadIdx.x] = m;
    }
    __syncthreads();
    mx = red[0][threadIdx.x];
    __syncthreads();

    float sum = 0.0f;
    for (int t = threadIdx.y; t < TLEN; t += 8) {
        float e = expf(p[(long)t * SEQ + s] - mx);
        p[(long)t * SEQ + s] = e;
        sum += e;
    }
    red[threadIdx.y][threadIdx.x] = sum;
    __syncthreads();
    if (threadIdx.y == 0) {
        float t = red[0][threadIdx.x];
        #pragma unroll
        for (int i = 1; i < 8; i++) t += red[i][threadIdx.x];
        red[0][threadIdx.x] = 1.0f / t;
    }
    __syncthreads();
    float rinv = red[0][threadIdx.x];
    for (int t = threadIdx.y; t < TLEN; t += 8) {
        p[(long)t * SEQ + s] *= rinv;
    }
}

// ---------------- silu(gate) * up, in place into gate ----------------
__global__ void silu_mul(float* __restrict__ gate, const float* __restrict__ up, int n) {
    int i = blockIdx.x * blockDim.x + threadIdx.x;
    if (i < n) {
        float g = gate[i];
        gate[i] = (g / (1.0f + expf(-g))) * up[i];
    }
}

// ---------------- host orchestration ----------------
extern "C" void kernel_launch(void* const* d_in, const int* in_sizes, int n_in,
                              void* d_out, int out_size) {
    const float* x_in     = (const float*)d_in[0];
    const int*   positions= (const int*)d_in[1];
    const int*   kvw      = (const int*)d_in[2];
    // d_in[3] self_attn_mask: equivalent mask recomputed from kv_write_index
    const int*   enc_len  = (const int*)d_in[4];
    const float* q_w      = (const float*)d_in[5];
    const float* k_w      = (const float*)d_in[6];
    const float* v_w      = (const float*)d_in[7];
    const float* o_w      = (const float*)d_in[8];
    const float* cq_w     = (const float*)d_in[9];
    const float* co_w     = (const float*)d_in[10];
    const float* sa_norm  = (const float*)d_in[11];
    const float* ca_norm  = (const float*)d_in[12];
    const float* mlp_norm = (const float*)d_in[13];
    const float* fin_norm = (const float*)d_in[14];
    const float* wg_w     = (const float*)d_in[15];
    const float* wu_w     = (const float*)d_in[16];
    const float* wd_w     = (const float*)d_in[17];
    const float* k_cache  = (const float*)d_in[18];
    const float* v_cache  = (const float*)d_in[19];
    const float* ck_cache = (const float*)d_in[20];
    const float* cv_cache = (const float*)d_in[21];

    float *px, *ph, *pq, *pk, *pv, *pkey, *pval, *psc, *pattn, *pcsc, *pgate, *pup;
    cudaGetSymbolAddress((void**)&px,    g_x);
    cudaGetSymbolAddress((void**)&ph,    g_h);
    cudaGetSymbolAddress((void**)&pq,    g_q);
    cudaGetSymbolAddress((void**)&pk,    g_k);
    cudaGetSymbolAddress((void**)&pv,    g_v);
    cudaGetSymbolAddress((void**)&pkey,  g_key);
    cudaGetSymbolAddress((void**)&pval,  g_val);
    cudaGetSymbolAddress((void**)&psc,   g_scores);
    cudaGetSymbolAddress((void**)&pattn, g_attn);
    cudaGetSymbolAddress((void**)&pcsc,  g_cscores);
    cudaGetSymbolAddress((void**)&pgate, g_gate);
    cudaGetSymbolAddress((void**)&pup,   g_up);

    const float scale  = 0.08838834764831845f;  // 1/sqrt(128)
    const float cscale = 0.08838834764831845f;

    dim3 blk16(16, 16);
    dim3 blk328(32, 8);

    // x -> g_x
    {
        int n = NB * DIM * SEQ;
        copy_kernel<<<(n + 255) / 256, 256>>>(x_in, px, n);
    }

    for (int l = 0; l < NLAYER; l++) {
        long wOffD2   = (long)l * DIM * DIM;      // 2048x2048 weights
        long wOffKV   = (long)l * DIM * (HKVN * HDN);
        long wOffFF   = (long)l * DIM * FFN;
        long wOffFFd  = (long)l * FFN * DIM;

        // ---- self attention ----
        rmsnorm_kernel<<<dim3(SEQ / 32, NB), blk328>>>(px, sa_norm + (long)l * DIM, ph);

        gemm_tn<<<dim3((HQN * HDN) / 64, SEQ / 64, NB), blk16>>>(
            q_w + wOffD2, ph, pq, DIM, HQN * HDN, SEQ,
            (long)DIM * SEQ, (long)HQN * HDN * SEQ, 0);
        gemm_tn<<<dim3((HKVN * HDN) / 64, SEQ / 64, NB), blk16>>>(
            k_w + wOffKV, ph, pk, DIM, HKVN * HDN, SEQ,
            (long)DIM * SEQ, (long)HKVN * HDN * SEQ, 0);
        gemm_tn<<<dim3((HKVN * HDN) / 64, SEQ / 64, NB), blk16>>>(
            v_w + wOffKV, ph, pv, DIM, HKVN * HDN, SEQ,
            (long)DIM * SEQ, (long)HKVN * HDN * SEQ, 0);

        {
            int nq = NB * HQN * 64 * SEQ;
            rope_kernel<<<(nq + 255) / 256, 256>>>(pq, positions, HQN);
            int nk = NB * HKVN * 64 * SEQ;
            rope_kernel<<<(nk + 255) / 256, 256>>>(pk, positions, HKVN);
        }

        {
            int n = NB * HKVN * ALEN * HDN;
            update_key<<<(n + 255) / 256, 256>>>(
                k_cache + (long)l * NB * HKVN * ALEN * HDN, pk, pkey, kvw);
            update_val<<<(n + 255) / 256, 256>>>(
                v_cache + (long)l * NB * HKVN * HDN * ALEN, pv, pval, kvw);
        }

        // scores[z][a][s], z = b*HQ + (k*G+g): key shared per (b,k) -> aDiv = GRP
        gemm_nn<<<dim3(ALEN / 64, SEQ / 64, NB * HQN), blk16>>>(
            pkey, pq, psc, HDN, ALEN, SEQ,
            (long)ALEN * HDN, GRP, (long)HDN * SEQ, (long)ALEN * SEQ);

        sa_softmax<<<dim3(SEQ / 32, NB * HQN), blk328>>>(psc, kvw, scale);

        gemm_nn<<<dim3(HDN / 64, SEQ / 64, NB * HQN), blk16>>>(
            pval, psc, pattn, ALEN, HDN, SEQ,
            (long)HDN * ALEN, GRP, (long)ALEN * SEQ, (long)HDN * SEQ);

        gemm_tn<<<dim3(DIM / 64, SEQ / 64, NB), blk16>>>(
            o_w + wOffD2, pattn, px, HQN * HDN, DIM, SEQ,
            (long)HQN * HDN * SEQ, (long)DIM * SEQ, 1);

        // ---- cross attention ----
        rmsnorm_kernel<<<dim3(SEQ / 32, NB), blk328>>>(px, ca_norm + (long)l * DIM, ph);

        gemm_tn<<<dim3((HCN * HDCN) / 64, SEQ / 64, NB), blk16>>>(
            cq_w + wOffD2, ph, pq, DIM, HCN * HDCN, SEQ,
            (long)DIM * SEQ, (long)HCN * HDCN * SEQ, 0);

        {
            int nq = NB * HCN * 64 * SEQ;
            rope_kernel<<<(nq + 255) / 256, 256>>>(pq, positions, HCN);
        }

        gemm_nn<<<dim3(TLEN / 64, SEQ / 64, NB * HCN), blk16>>>(
            ck_cache + (long)l * NB * HCN * TLEN * HDCN, pq, pcsc, HDCN, TLEN, SEQ,
            (long)TLEN * HDCN, 1, (long)HDCN * SEQ, (long)TLEN * SEQ);

        ca_softmax<<<dim3(SEQ / 32, NB * HCN), blk328>>>(pcsc, enc_len, cscale);

        gemm_nn<<<dim3(HDCN / 64, SEQ / 64, NB * HCN), blk16>>>(
            cv_cache + (long)l * NB * HCN * HDCN * TLEN, pcsc, pattn, TLEN, HDCN, SEQ,
            (long)HDCN * TLEN, 1, (long)TLEN * SEQ, (long)HDCN * SEQ);

        gemm_tn<<<dim3(DIM / 64, SEQ / 64, NB), blk16>>>(
            co_w + wOffD2, pattn, px, HCN * HDCN, DIM, SEQ,
            (long)HCN * HDCN * SEQ, (long)DIM * SEQ, 1);

        // ---- MLP ----
        rmsnorm_kernel<<<dim3(SEQ / 32, NB), blk328>>>(px, mlp_norm + (long)l * DIM, ph);

        gemm_tn<<<dim3(FFN / 64, SEQ / 64, NB), blk16>>>(
            wg_w + wOffFF, ph, pgate, DIM, FFN, SEQ,
            (long)DIM * SEQ, (long)FFN * SEQ, 0);
        gemm_tn<<<dim3(FFN / 64, SEQ / 64, NB), blk16>>>(
            wu_w + wOffFF, ph, pup, DIM, FFN, SEQ,
            (long)DIM * SEQ, (long)FFN * SEQ, 0);

        {
            int n = NB * FFN * SEQ;
            silu_mul<<<(n + 255) / 256, 256>>>(pgate, pup, n);
        }

        gemm_tn<<<dim3(DIM / 64, SEQ / 64, NB), blk16>>>(
            wd_w + wOffFFd, pgate, px, FFN, DIM, SEQ,
            (long)FFN * SEQ, (long)DIM * SEQ, 1);
    }

    // final norm directly into d_out (same layout as x)
    rmsnorm_kernel<<<dim3(SEQ / 32, NB), blk328>>>(px, fin_norm, (float*)d_out);
}

// round 2
// speedup vs baseline: 2.8894x; 2.8894x over previous
#include <cuda_runtime.h>
#include <math.h>
#include <stdint.h>

// ---------------- problem constants ----------------
#define NB     2
#define DIM    2048
#define SEQ    128
#define ALEN   1536
#define TLEN   512
#define HQN    16
#define HKVN   4
#define HDN    128
#define HCN    16
#define HDCN   128
#define FFN    8192
#define NLAYER 2
#define GRP    (HQN / HKVN)   // 4
#define NEGV   (-30000.0f)
#define EPSV   (1e-5f)

// ---------------- device scratch (static, no allocation) ----------------
__device__ float g_x[NB * DIM * SEQ];
__device__ float g_h[NB * DIM * SEQ];
__device__ float g_q[NB * HQN * HDN * SEQ];
__device__ float g_k[NB * HKVN * HDN * SEQ];
__device__ float g_v[NB * HKVN * HDN * SEQ];
__device__ float g_key[NB * HKVN * ALEN * HDN];
__device__ float g_val[NB * HKVN * HDN * ALEN];
__device__ float g_scores[NB * HQN * ALEN * SEQ];
__device__ float g_attn[NB * HQN * HDN * SEQ];
__device__ float g_cscores[NB * HCN * TLEN * SEQ];
__device__ float g_gate[NB * FFN * SEQ];
__device__ float g_up[NB * FFN * SEQ];
__device__ float g_part[2097152];   // split-K partials (max z*split*M*N = 2*4*2048*128)

// ---------------- helpers ----------------
__device__ __forceinline__ uint32_t f2tf(float f) {
    uint32_t u;
    asm("cvt.rna.tf32.f32 %0, %1;" : "=r"(u) : "f"(f));
    return u;
}

__device__ __forceinline__ void mma_tf32(float* c, const uint32_t* a, const uint32_t* b) {
    asm volatile(
        "mma.sync.aligned.m16n8k8.row.col.f32.tf32.tf32.f32 "
        "{%0,%1,%2,%3}, {%4,%5,%6,%7}, {%8,%9}, {%0,%1,%2,%3};\n"
        : "+f"(c[0]), "+f"(c[1]), "+f"(c[2]), "+f"(c[3])
        : "r"(a[0]), "r"(a[1]), "r"(a[2]), "r"(a[3]), "r"(b[0]), "r"(b[1]));
}

// ---------------- unified TF32 tensor-core GEMM ----------------
// C[m,n] = sum_k A(k,m) * B[k*ldb+n], N fixed at 128 (= SEQ), one N-block.
// modeTN=1: A stored K x M (A[k*lda+m]); modeTN=0: A stored M x K (A[m*lda+k]).
// Batch z: A offset (z/aDiv)*strideA, B offset z*strideB, C offset z*strideC.
// split>1: blockIdx.y selects a K-chunk; partial written to part[(z*split+ks)][M][128].
// BM=128, BK=16; 256 thr = 8 warps (2M x 4N), warp tile 64x32 (m16x4, n8x4).
__global__ __launch_bounds__(256, 1) void gemm_mma(
    const float* __restrict__ A, const float* __restrict__ Bm, float* __restrict__ C,
    int K, int M, int lda, int ldb, int ldc,
    long strideA, int aDiv, long strideB, long strideC,
    int accum, int modeTN, int split, float* __restrict__ part)
{
    __shared__ uint32_t As[16][136];
    __shared__ uint32_t Bs[16][136];

    const int z  = blockIdx.z;
    const int ks = blockIdx.y;
    const int bm = blockIdx.x * 128;
    const int kChunk = K / split;
    const int k0 = ks * kChunk;
    const int nT = kChunk / 16;

    const float* Ab = A + (long)(z / aDiv) * strideA;
    const float* Bb = Bm + (long)z * strideB;

    const int tid  = threadIdx.x;
    const int warp = tid >> 5, lane = tid & 31;
    const int wm = (warp & 1) * 64;
    const int wn = (warp >> 1) * 32;
    const int gid = lane >> 2, tig = lane & 3;

    float acc[4][4][4];
    #pragma unroll
    for (int i = 0; i < 4; i++)
        #pragma unroll
        for (int j = 0; j < 4; j++)
            #pragma unroll
            for (int r = 0; r < 4; r++) acc[i][j][r] = 0.0f;

    float ra[8], rb[8];

    // initial tile load (global -> regs)
    {
        int kAbs = k0;
        if (modeTN) {
            #pragma unroll
            for (int i = 0; i < 8; i++) {
                int t = tid + (i << 8);
                ra[i] = Ab[(long)(kAbs + (t >> 7)) * lda + bm + (t & 127)];
            }
        } else {
            #pragma unroll
            for (int i = 0; i < 8; i++) {
                int t = tid + (i << 8);
                ra[i] = Ab[(long)(bm + (t >> 4)) * lda + kAbs + (t & 15)];
            }
        }
        #pragma unroll
        for (int i = 0; i < 8; i++) {
            int t = tid + (i << 8);
            rb[i] = Bb[(long)(kAbs + (t >> 7)) * ldb + (t & 127)];
        }
    }

    for (int t0 = 0; t0 < nT; t0++) {
        __syncthreads();
        // regs -> smem (with tf32 convert)
        if (modeTN) {
            #pragma unroll
            for (int i = 0; i < 8; i++) {
                int t = tid + (i << 8);
                As[t >> 7][t & 127] = f2tf(ra[i]);
            }
        } else {
            #pragma unroll
            for (int i = 0; i < 8; i++) {
                int t = tid + (i << 8);
                As[t & 15][t >> 4] = f2tf(ra[i]);
            }
        }
        #pragma unroll
        for (int i = 0; i < 8; i++) {
            int t = tid + (i << 8);
            Bs[t >> 7][t & 127] = f2tf(rb[i]);
        }
        __syncthreads();

        // prefetch next tile
        if (t0 + 1 < nT) {
            int kAbs = k0 + (t0 + 1) * 16;
            if (modeTN) {
                #pragma unroll
                for (int i = 0; i < 8; i++) {
                    int t = tid + (i << 8);
                    ra[i] = Ab[(long)(kAbs + (t >> 7)) * lda + bm + (t & 127)];
                }
            } else {
                #pragma unroll
                for (int i = 0; i < 8; i++) {
                    int t = tid + (i << 8);
                    ra[i] = Ab[(long)(bm + (t >> 4)) * lda + kAbs + (t & 15)];
                }
            }
            #pragma unroll
            for (int i = 0; i < 8; i++) {
                int t = tid + (i << 8);
                rb[i] = Bb[(long)(kAbs + (t >> 7)) * ldb + (t & 127)];
            }
        }

        // compute 2 x k8 steps
        #pragma unroll
        for (int kh = 0; kh < 2; kh++) {
            const int kb = kh * 8;
            uint32_t aF[4][4], bF[4][2];
            #pragma unroll
            for (int i = 0; i < 4; i++) {
                int r0 = wm + i * 16 + gid;
                aF[i][0] = As[kb + tig][r0];
                aF[i][1] = As[kb + tig][r0 + 8];
                aF[i][2] = As[kb + tig + 4][r0];
                aF[i][3] = As[kb + tig + 4][r0 + 8];
            }
            #pragma unroll
            for (int j = 0; j < 4; j++) {
                int c0 = wn + j * 8 + gid;
                bF[j][0] = Bs[kb + tig][c0];
                bF[j][1] = Bs[kb + tig + 4][c0];
            }
            #pragma unroll
            for (int i = 0; i < 4; i++)
                #pragma unroll
                for (int j = 0; j < 4; j++)
                    mma_tf32(acc[i][j], aF[i], bF[j]);
        }
    }

    // epilogue
    if (split == 1) {
        float* Cb = C + (long)z * strideC;
        #pragma unroll
        for (int i = 0; i < 4; i++) {
            int row = bm + wm + i * 16 + gid;
            #pragma unroll
            for (int j = 0; j < 4; j++) {
                int col = wn + j * 8 + 2 * tig;
                long i0 = (long)row * ldc + col;
                long i1 = (long)(row + 8) * ldc + col;
                if (accum) {
                    Cb[i0]     += acc[i][j][0];
                    Cb[i0 + 1] += acc[i][j][1];
                    Cb[i1]     += acc[i][j][2];
                    Cb[i1 + 1] += acc[i][j][3];
                } else {
                    Cb[i0]     = acc[i][j][0];
                    Cb[i0 + 1] = acc[i][j][1];
                    Cb[i1]     = acc[i][j][2];
                    Cb[i1 + 1] = acc[i][j][3];
                }
            }
        }
    } else {
        float* Pb = part + ((long)(z * split + ks) * M) * 128;
        #pragma unroll
        for (int i = 0; i < 4; i++) {
            int row = bm + wm + i * 16 + gid;
            #pragma unroll
            for (int j = 0; j < 4; j++) {
                int col = wn + j * 8 + 2 * tig;
                long i0 = (long)row * 128 + col;
                long i1 = (long)(row + 8) * 128 + col;
                Pb[i0]     = acc[i][j][0];
                Pb[i0 + 1] = acc[i][j][1];
                Pb[i1]     = acc[i][j][2];
                Pb[i1 + 1] = acc[i][j][3];
            }
        }
    }
}

// deterministic split-K reduction: C[i] = (accum ? C[i] : 0) + sum_s part[..]
__global__ void reduce_split(const float* __restrict__ part, float* __restrict__ C,
                             long MN, int split, int accum, long total) {
    long i = (long)blockIdx.x * blockDim.x + threadIdx.x;
    if (i >= total) return;
    long zi = i / MN, mn = i % MN;
    float s = accum ? C[i] : 0.0f;
    for (int k = 0; k < split; k++) s += part[(zi * (long)split + k) * MN + mn];
    C[i] = s;
}

// ---------------- elementwise copy ----------------
__global__ void copy_kernel(const float* __restrict__ src, float* __restrict__ dst, int n) {
    int i = blockIdx.x * blockDim.x + threadIdx.x;
    if (i < n) dst[i] = src[i];
}

// ---------------- RMSNorm over D for each (b, s); s-major coalesced ----------------
__global__ void rmsnorm_kernel(const float* __restrict__ x, const float* __restrict__ w,
                               float* __restrict__ out) {
    int s = blockIdx.x * 32 + threadIdx.x;
    int b = blockIdx.y;
    const float* xb = x + (long)b * DIM * SEQ;
    float* ob = out + (long)b * DIM * SEQ;
    float ss = 0.0f;
    for (int d = threadIdx.y; d < DIM; d += 8) {
        float v = xb[d * SEQ + s];
        ss += v * v;
    }
    __shared__ float red[8][33];
    red[threadIdx.y][threadIdx.x] = ss;
    __syncthreads();
    if (threadIdx.y == 0) {
        float tot = 0.0f;
        #pragma unroll
        for (int i = 0; i < 8; i++) tot += red[i][threadIdx.x];
        red[0][threadIdx.x] = rsqrtf(tot / (float)DIM + EPSV);
    }
    __syncthreads();
    float inv = red[0][threadIdx.x];
    for (int d = threadIdx.y; d < DIM; d += 8) {
        ob[d * SEQ + s] = xb[d * SEQ + s] * inv * w[d];
    }
}

// ---------------- RoPE in-place on (B, H, 128, S) buffer ----------------
__global__ void rope_kernel(float* __restrict__ q, const int* __restrict__ positions, int H) {
    int idx = blockIdx.x * blockDim.x + threadIdx.x;
    int total = NB * H * 64 * SEQ;
    if (idx >= total) return;
    int s = idx % SEQ;
    int i = (idx / SEQ) % 64;
    int h = (idx / (SEQ * 64)) % H;
    int b = idx / (SEQ * 64 * H);
    float pos = (float)positions[b * SEQ + s];
    float inv = powf(10000.0f, -(float)i / 64.0f);
    float sn, cs;
    sincosf(pos * inv, &sn, &cs);
    long base = (((long)b * H + h) * HDN) * SEQ;
    float x1 = q[base + (long)i * SEQ + s];
    float x2 = q[base + (long)(i + 64) * SEQ + s];
    q[base + (long)i * SEQ + s] = x1 * cs - x2 * sn;
    q[base + (long)(i + 64) * SEQ + s] = x2 * cs + x1 * sn;
}

// ---------------- merge k into key scratch: key[b,k,a,d] ----------------
__global__ void update_key(const float* __restrict__ kc, const float* __restrict__ knew,
                           float* __restrict__ keybuf, const int* __restrict__ wptr) {
    int idx = blockIdx.x * blockDim.x + threadIdx.x;
    const int total = NB * HKVN * ALEN * HDN;
    if (idx >= total) return;
    int w = wptr[0];
    int d = idx % HDN;
    int a = (idx / HDN) % ALEN;
    int kh = (idx / (HDN * ALEN)) % HKVN;
    int b = idx / (HDN * ALEN * HKVN);
    float v;
    if (a >= w && a < w + SEQ) {
        v = knew[(((long)b * HKVN + kh) * HDN + d) * SEQ + (a - w)];
    } else {
        v = kc[idx];
    }
    keybuf[idx] = v;
}

// ---------------- merge v into val scratch: val[b,k,d,a] ----------------
__global__ void update_val(const float* __restrict__ vc, const float* __restrict__ vnew,
                           float* __restrict__ valbuf, const int* __restrict__ wptr) {
    int idx = blockIdx.x * blockDim.x + threadIdx.x;
    const int total = NB * HKVN * HDN * ALEN;
    if (idx >= total) return;
    int w = wptr[0];
    int a = idx % ALEN;
    int d = (idx / ALEN) % HDN;
    int kh = (idx / (ALEN * HDN)) % HKVN;
    int b = idx / (ALEN * HDN * HKVN);
    float v;
    if (a >= w && a < w + SEQ) {
        v = vnew[(((long)b * HKVN + kh) * HDN + d) * SEQ + (a - w)];
    } else {
        v = vc[idx];
    }
    valbuf[idx] = v;
}

// ---------------- self-attn softmax over a ----------------
__global__ void sa_softmax(float* __restrict__ sc, const int* __restrict__ wptr, float scale) {
    int s = blockIdx.x * 32 + threadIdx.x;
    int z = blockIdx.y;
    int w = wptr[0];
    float* p = sc + (long)z * ALEN * SEQ;
    __shared__ float red[8][33];

    float mx = -3.0e38f;
    for (int a = threadIdx.y; a < ALEN; a += 8) {
        float v = p[(long)a * SEQ + s] * scale;
        if (a > w + s) v += NEGV;
        p[(long)a * SEQ + s] = v;
        mx = fmaxf(mx, v);
    }
    red[threadIdx.y][threadIdx.x] = mx;
    __syncthreads();
    if (threadIdx.y == 0) {
        float m = red[0][threadIdx.x];
        #pragma unroll
        for (int i = 1; i < 8; i++) m = fmaxf(m, red[i][threadIdx.x]);
        red[0][threadIdx.x] = m;
    }
    __syncthreads();
    mx = red[0][threadIdx.x];
    __syncthreads();

    float sum = 0.0f;
    for (int a = threadIdx.y; a < ALEN; a += 8) {
        float e = expf(p[(long)a * SEQ + s] - mx);
        p[(long)a * SEQ + s] = e;
        sum += e;
    }
    red[threadIdx.y][threadIdx.x] = sum;
    __syncthreads();
    if (threadIdx.y == 0) {
        float t = red[0][threadIdx.x];
        #pragma unroll
        for (int i = 1; i < 8; i++) t += red[i][threadIdx.x];
        red[0][threadIdx.x] = 1.0f / t;
    }
    __syncthreads();
    float rinv = red[0][threadIdx.x];
    for (int a = threadIdx.y; a < ALEN; a += 8) {
        p[(long)a * SEQ + s] *= rinv;
    }
}

// ---------------- cross-attn softmax over t ----------------
__global__ void ca_softmax(float* __restrict__ sc, const int* __restrict__ enc, float scale) {
    int s = blockIdx.x * 32 + threadIdx.x;
    int z = blockIdx.y;
    int b = z / HCN;
    int len = enc[b];
    float* p = sc + (long)z * TLEN * SEQ;
    __shared__ float red[8][33];

    float mx = -3.0e38f;
    for (int t = threadIdx.y; t < TLEN; t += 8) {
        float v = p[(long)t * SEQ + s] * scale;
        if (t >= len) v += NEGV;
        p[(long)t * SEQ + s] = v;
        mx = fmaxf(mx, v);
    }
    red[threadIdx.y][threadIdx.x] = mx;
    __syncthreads();
    if (threadIdx.y == 0) {
        float m = red[0][threadIdx.x];
        #pragma unroll
        for (int i = 1; i < 8; i++) m = fmaxf(m, red[i][threadIdx.x]);
        red[0][threadIdx.x] = m;
    }
    __syncthreads();
    mx = red[0][threadIdx.x];
    __syncthreads();

    float sum = 0.0f;
    for (int t = threadIdx.y; t < TLEN; t += 8) {
        float e = expf(p[(long)t * SEQ + s] - mx);
        p[(long)t * SEQ + s] = e;
        sum += e;
    }
    red[threadIdx.y][threadIdx.x] = sum;
    __syncthreads();
    if (threadIdx.y == 0) {
        float t = red[0][threadIdx.x];
        #pragma unroll
        for (int i = 1; i < 8; i++) t += red[i][threadIdx.x];
        red[0][threadIdx.x] = 1.0f / t;
    }
    __syncthreads();
    float rinv = red[0][threadIdx.x];
    for (int t = threadIdx.y; t < TLEN; t += 8) {
        p[(long)t * SEQ + s] *= rinv;
    }
}

// ---------------- silu(gate) * up, in place into gate ----------------
__global__ void silu_mul(float* __restrict__ gate, const float* __restrict__ up, int n) {
    int i = blockIdx.x * blockDim.x + threadIdx.x;
    if (i < n) {
        float g = gate[i];
        gate[i] = (g / (1.0f + expf(-g))) * up[i];
    }
}

// ---------------- host orchestration ----------------
extern "C" void kernel_launch(void* const* d_in, const int* in_sizes, int n_in,
                              void* d_out, int out_size) {
    const float* x_in     = (const float*)d_in[0];
    const int*   positions= (const int*)d_in[1];
    const int*   kvw      = (const int*)d_in[2];
    const int*   enc_len  = (const int*)d_in[4];
    const float* q_w      = (const float*)d_in[5];
    const float* k_w      = (const float*)d_in[6];
    const float* v_w      = (const float*)d_in[7];
    const float* o_w      = (const float*)d_in[8];
    const float* cq_w     = (const float*)d_in[9];
    const float* co_w     = (const float*)d_in[10];
    const float* sa_norm  = (const float*)d_in[11];
    const float* ca_norm  = (const float*)d_in[12];
    const float* mlp_norm = (const float*)d_in[13];
    const float* fin_norm = (const float*)d_in[14];
    const float* wg_w     = (const float*)d_in[15];
    const float* wu_w     = (const float*)d_in[16];
    const float* wd_w     = (const float*)d_in[17];
    const float* k_cache  = (const float*)d_in[18];
    const float* v_cache  = (const float*)d_in[19];
    const float* ck_cache = (const float*)d_in[20];
    const float* cv_cache = (const float*)d_in[21];

    float *px, *ph, *pq, *pk, *pv, *pkey, *pval, *psc, *pattn, *pcsc, *pgate, *pup, *ppart;
    cudaGetSymbolAddress((void**)&px,    g_x);
    cudaGetSymbolAddress((void**)&ph,    g_h);
    cudaGetSymbolAddress((void**)&pq,    g_q);
    cudaGetSymbolAddress((void**)&pk,    g_k);
    cudaGetSymbolAddress((void**)&pv,    g_v);
    cudaGetSymbolAddress((void**)&pkey,  g_key);
    cudaGetSymbolAddress((void**)&pval,  g_val);
    cudaGetSymbolAddress((void**)&psc,   g_scores);
    cudaGetSymbolAddress((void**)&pattn, g_attn);
    cudaGetSymbolAddress((void**)&pcsc,  g_cscores);
    cudaGetSymbolAddress((void**)&pgate, g_gate);
    cudaGetSymbolAddress((void**)&pup,   g_up);
    cudaGetSymbolAddress((void**)&ppart, g_part);

    const float scale  = 0.08838834764831845f;  // 1/sqrt(128)
    dim3 blk328(32, 8);

    {
        int n = NB * DIM * SEQ;
        copy_kernel<<<(n + 255) / 256, 256>>>(x_in, px, n);
    }

    for (int l = 0; l < NLAYER; l++) {
        long wOffD2   = (long)l * DIM * DIM;
        long wOffKV   = (long)l * DIM * (HKVN * HDN);
        long wOffFF   = (long)l * DIM * FFN;
        long wOffFFd  = (long)l * FFN * DIM;
        long cOffK    = (long)l * NB * HCN * TLEN * HDCN;
        long cOffV    = (long)l * NB * HCN * HDCN * TLEN;

        // ---- self attention ----
        rmsnorm_kernel<<<dim3(SEQ / 32, NB), blk328>>>(px, sa_norm + (long)l * DIM, ph);

        // q: TN, K=2048, M=2048, split=4
        gemm_mma<<<dim3(16, 4, NB), 256>>>(q_w + wOffD2, ph, pq,
            DIM, 2048, 2048, SEQ, SEQ, 0, 1, (long)DIM * SEQ, 0, 0, 1, 4, ppart);
        reduce_split<<<(NB * 2048 * 128 + 255) / 256, 256>>>(ppart, pq, 2048L * 128, 4, 0, (long)NB * 2048 * 128);
        // k: TN, M=512, split=16
        gemm_mma<<<dim3(4, 16, NB), 256>>>(k_w + wOffKV, ph, pk,
            DIM, 512, 512, SEQ, SEQ, 0, 1, (long)DIM * SEQ, 0, 0, 1, 16, ppart);
        reduce_split<<<(NB * 512 * 128 + 255) / 256, 256>>>(ppart, pk, 512L * 128, 16, 0, (long)NB * 512 * 128);
        // v
        gemm_mma<<<dim3(4, 16, NB), 256>>>(v_w + wOffKV, ph, pv,
            DIM, 512, 512, SEQ, SEQ, 0, 1, (long)DIM * SEQ, 0, 0, 1, 16, ppart);
        reduce_split<<<(NB * 512 * 128 + 255) / 256, 256>>>(ppart, pv, 512L * 128, 16, 0, (long)NB * 512 * 128);

        {
            int nq = NB * HQN * 64 * SEQ;
            rope_kernel<<<(nq + 255) / 256, 256>>>(pq, positions, HQN);
            int nk = NB * HKVN * 64 * SEQ;
            rope_kernel<<<(nk + 255) / 256, 256>>>(pk, positions, HKVN);
        }
        {
            int n = NB * HKVN * ALEN * HDN;
            update_key<<<(n + 255) / 256, 256>>>(
                k_cache + (long)l * NB * HKVN * ALEN * HDN, pk, pkey, kvw);
            update_val<<<(n + 255) / 256, 256>>>(
                v_cache + (long)l * NB * HKVN * HDN * ALEN, pv, pval, kvw);
        }

        // scores: NN, A=key (lda=128), K=128, M=1536, z=32, split=1
        gemm_mma<<<dim3(12, 1, NB * HQN), 256>>>(pkey, pq, psc,
            HDN, ALEN, HDN, SEQ, SEQ, (long)ALEN * HDN, GRP, (long)HDN * SEQ, (long)ALEN * SEQ, 0, 0, 1, ppart);

        sa_softmax<<<dim3(SEQ / 32, NB * HQN), blk328>>>(psc, kvw, scale);

        // attn = val @ probs: NN, A=val (lda=1536), K=1536, M=128, split=4
        gemm_mma<<<dim3(1, 4, NB * HQN), 256>>>(pval, psc, pattn,
            ALEN, HDN, ALEN, SEQ, SEQ, (long)HDN * ALEN, GRP, (long)ALEN * SEQ, 0, 0, 0, 4, ppart);
        reduce_split<<<(32 * 128 * 128 + 255) / 256, 256>>>(ppart, pattn, 128L * 128, 4, 0, 32L * 128 * 128);

        // o: TN, K=2048, M=2048, split=4, accumulate into x via reduce
        gemm_mma<<<dim3(16, 4, NB), 256>>>(o_w + wOffD2, pattn, px,
            HQN * HDN, DIM, DIM, SEQ, SEQ, 0, 1, (long)HQN * HDN * SEQ, 0, 0, 1, 4, ppart);
        reduce_split<<<(NB * 2048 * 128 + 255) / 256, 256>>>(ppart, px, 2048L * 128, 4, 1, (long)NB * 2048 * 128);

        // ---- cross attention ----
        rmsnorm_kernel<<<dim3(SEQ / 32, NB), blk328>>>(px, ca_norm + (long)l * DIM, ph);

        gemm_mma<<<dim3(16, 4, NB), 256>>>(cq_w + wOffD2, ph, pq,
            DIM, 2048, 2048, SEQ, SEQ, 0, 1, (long)DIM * SEQ, 0, 0, 1, 4, ppart);
        reduce_split<<<(NB * 2048 * 128 + 255) / 256, 256>>>(ppart, pq, 2048L * 128, 4, 0, (long)NB * 2048 * 128);
        {
            int nq = NB * HCN * 64 * SEQ;
            rope_kernel<<<(nq + 255) / 256, 256>>>(pq, positions, HCN);
        }

        // cscores: NN, A=ck (lda=128), K=128, M=512, z=32, split=1
        gemm_mma<<<dim3(4, 1, NB * HCN), 256>>>(ck_cache + cOffK, pq, pcsc,
            HDCN, TLEN, HDCN, SEQ, SEQ, (long)TLEN * HDCN, 1, (long)HDCN * SEQ, (long)TLEN * SEQ, 0, 0, 1, ppart);

        ca_softmax<<<dim3(SEQ / 32, NB * HCN), blk328>>>(pcsc, enc_len, scale);

        // cattn: NN, A=cv (lda=512), K=512, M=128, split=4
        gemm_mma<<<dim3(1, 4, NB * HCN), 256>>>(cv_cache + cOffV, pcsc, pattn,
            TLEN, HDCN, TLEN, SEQ, SEQ, (long)HDCN * TLEN, 1, (long)TLEN * SEQ, 0, 0, 0, 4, ppart);
        reduce_split<<<(32 * 128 * 128 + 255) / 256, 256>>>(ppart, pattn, 128L * 128, 4, 0, 32L * 128 * 128);

        // co: accumulate into x
        gemm_mma<<<dim3(16, 4, NB), 256>>>(co_w + wOffD2, pattn, px,
            HCN * HDCN, DIM, DIM, SEQ, SEQ, 0, 1, (long)HCN * HDCN * SEQ, 0, 0, 1, 4, ppart);
        reduce_split<<<(NB * 2048 * 128 + 255) / 256, 256>>>(ppart, px, 2048L * 128, 4, 1, (long)NB * 2048 * 128);

        // ---- MLP ----
        rmsnorm_kernel<<<dim3(SEQ / 32, NB), blk328>>>(px, mlp_norm + (long)l * DIM, ph);

        gemm_mma<<<dim3(64, 1, NB), 256>>>(wg_w + wOffFF, ph, pgate,
            DIM, FFN, FFN, SEQ, SEQ, 0, 1, (long)DIM * SEQ, (long)FFN * SEQ, 0, 1, 1, ppart);
        gemm_mma<<<dim3(64, 1, NB), 256>>>(wu_w + wOffFF, ph, pup,
            DIM, FFN, FFN, SEQ, SEQ, 0, 1, (long)DIM * SEQ, (long)FFN * SEQ, 0, 1, 1, ppart);
        {
            int n = NB * FFN * SEQ;
            silu_mul<<<(n + 255) / 256, 256>>>(pgate, pup, n);
        }
        // down: TN, K=8192, M=2048, split=4, accumulate into x via reduce
        gemm_mma<<<dim3(16, 4, NB), 256>>>(wd_w + wOffFFd, pgate, px,
            FFN, DIM, DIM, SEQ, SEQ, 0, 1, (long)FFN * SEQ, 0, 0, 1, 4, ppart);
        reduce_split<<<(NB * 2048 * 128 + 255) / 256, 256>>>(ppart, px, 2048L * 128, 4, 1, (long)NB * 2048 * 128);
    }

    rmsnorm_kernel<<<dim3(SEQ / 32, NB), blk328>>>(px, fin_norm, (float*)d_out);
}

// round 3
// speedup vs baseline: 3.1973x; 1.1066x over previous
#include <cuda_runtime.h>
#include <math.h>
#include <stdint.h>

// ---------------- problem constants ----------------
#define NB     2
#define DIM    2048
#define SEQ    128
#define ALEN   1536
#define TLEN   512
#define HQN    16
#define HKVN   4
#define HDN    128
#define HCN    16
#define HDCN   128
#define FFN    8192
#define NLAYER 2
#define GRP    (HQN / HKVN)   // 4
#define NEGV   (-30000.0f)
#define EPSV   (1e-5f)

// ---------------- device scratch (static, no allocation) ----------------
__device__ float g_x[NB * DIM * SEQ];
__device__ float g_h[NB * DIM * SEQ];
__device__ float g_q[NB * HQN * HDN * SEQ];
__device__ float g_k[NB * HKVN * HDN * SEQ];
__device__ float g_v[NB * HKVN * HDN * SEQ];
__device__ float g_key[NB * HKVN * ALEN * HDN];
__device__ float g_val[NB * HKVN * HDN * ALEN];
__device__ float g_scores[NB * HQN * ALEN * SEQ];
__device__ float g_attn[NB * HQN * HDN * SEQ];
__device__ float g_cscores[NB * HCN * TLEN * SEQ];
__device__ float g_gate[NB * FFN * SEQ];
__device__ float g_up[NB * FFN * SEQ];
__device__ float g_part[8388608];   // split-K partials (max 2*16*2048*128)

// ---------------- helpers ----------------
__device__ __forceinline__ uint32_t f2tf(float f) {
    uint32_t u;
    asm("cvt.rna.tf32.f32 %0, %1;" : "=r"(u) : "f"(f));
    return u;
}

__device__ __forceinline__ void mma_tf32(float* c, const uint32_t* a, const uint32_t* b) {
    asm volatile(
        "mma.sync.aligned.m16n8k8.row.col.f32.tf32.tf32.f32 "
        "{%0,%1,%2,%3}, {%4,%5,%6,%7}, {%8,%9}, {%0,%1,%2,%3};\n"
        : "+f"(c[0]), "+f"(c[1]), "+f"(c[2]), "+f"(c[3])
        : "r"(a[0]), "r"(a[1]), "r"(a[2]), "r"(a[3]), "r"(b[0]), "r"(b[1]));
}

// ---------------- unified TF32 tensor-core GEMM (double-buffered) ----------------
// C[m,n] = sum_k A(k,m) * B[k*ldb+n], N fixed at 128 (= SEQ), one N-block.
// modeTN=1: A stored K x M; modeTN=0: A stored M x K.
// Batch z: A offset (z/aDiv)*strideA, B offset z*strideB, C offset z*strideC.
// split>1: blockIdx.y = K-chunk; partial to part[(z*split+ks)*M*128 ...].
// BM=128, BK=16; 256 thr = 8 warps (2M x 4N), warp tile 64x32.
__global__ __launch_bounds__(256, 2) void gemm_mma(
    const float* __restrict__ A, const float* __restrict__ Bm, float* __restrict__ C,
    int K, int M, int lda, int ldb, int ldc,
    long strideA, int aDiv, long strideB, long strideC,
    int accum, int modeTN, int split, float* __restrict__ part)
{
    __shared__ uint32_t As[2][16][136];
    __shared__ uint32_t Bs[2][16][136];

    const int z  = blockIdx.z;
    const int ks = blockIdx.y;
    const int bm = blockIdx.x * 128;
    const int kChunk = K / split;
    const int k0 = ks * kChunk;
    const int nT = kChunk / 16;

    const float* Ab = A + (long)(z / aDiv) * strideA;
    const float* Bb = Bm + (long)z * strideB;

    const int tid  = threadIdx.x;
    const int warp = tid >> 5, lane = tid & 31;
    const int wm = (warp & 1) * 64;
    const int wn = (warp >> 1) * 32;
    const int gid = lane >> 2, tig = lane & 3;

    // load geometry
    const int rA = tid >> 5;          // 0..7 (row within 16-row K-tile, +8 for second)
    const int cA = (tid & 31) * 4;    // 0..124 (col)
    const int mA = tid >> 2;          // 0..63 (NN-mode row, +64 for second)
    const int kA = (tid & 3) * 4;     // 0..12 (NN-mode k col)

    float acc[4][4][4] = {};
    float4 a0, a1, b0, b1;

#define LDG_TILE(kAbs) do {                                                        \
    if (modeTN) {                                                                  \
        a0 = *(const float4*)&Ab[(long)((kAbs) + rA) * lda + bm + cA];             \
        a1 = *(const float4*)&Ab[(long)((kAbs) + rA + 8) * lda + bm + cA];         \
    } else {                                                                       \
        a0 = *(const float4*)&Ab[(long)(bm + mA) * lda + (kAbs) + kA];             \
        a1 = *(const float4*)&Ab[(long)(bm + mA + 64) * lda + (kAbs) + kA];        \
    }                                                                              \
    b0 = *(const float4*)&Bb[(long)((kAbs) + rA) * ldb + cA];                      \
    b1 = *(const float4*)&Bb[(long)((kAbs) + rA + 8) * ldb + cA];                  \
} while (0)

#define STS_TILE(buf) do {                                                         \
    if (modeTN) {                                                                  \
        As[buf][rA][cA + 0] = f2tf(a0.x); As[buf][rA][cA + 1] = f2tf(a0.y);        \
        As[buf][rA][cA + 2] = f2tf(a0.z); As[buf][rA][cA + 3] = f2tf(a0.w);        \
        As[buf][rA + 8][cA + 0] = f2tf(a1.x); As[buf][rA + 8][cA + 1] = f2tf(a1.y);\
        As[buf][rA + 8][cA + 2] = f2tf(a1.z); As[buf][rA + 8][cA + 3] = f2tf(a1.w);\
    } else {                                                                       \
        As[buf][kA + 0][mA] = f2tf(a0.x); As[buf][kA + 1][mA] = f2tf(a0.y);        \
        As[buf][kA + 2][mA] = f2tf(a0.z); As[buf][kA + 3][mA] = f2tf(a0.w);        \
        As[buf][kA + 0][mA + 64] = f2tf(a1.x); As[buf][kA + 1][mA + 64] = f2tf(a1.y);\
        As[buf][kA + 2][mA + 64] = f2tf(a1.z); As[buf][kA + 3][mA + 64] = f2tf(a1.w);\
    }                                                                              \
    Bs[buf][rA][cA + 0] = f2tf(b0.x); Bs[buf][rA][cA + 1] = f2tf(b0.y);            \
    Bs[buf][rA][cA + 2] = f2tf(b0.z); Bs[buf][rA][cA + 3] = f2tf(b0.w);            \
    Bs[buf][rA + 8][cA + 0] = f2tf(b1.x); Bs[buf][rA + 8][cA + 1] = f2tf(b1.y);    \
    Bs[buf][rA + 8][cA + 2] = f2tf(b1.z); Bs[buf][rA + 8][cA + 3] = f2tf(b1.w);    \
} while (0)

    LDG_TILE(k0);
    STS_TILE(0);
    __syncthreads();
    if (nT > 1) LDG_TILE(k0 + 16);

    for (int t = 0; t < nT; t++) {
        const int cur = t & 1;
        #pragma unroll
        for (int kh = 0; kh < 2; kh++) {
            const int kb = kh * 8;
            uint32_t aF[4][4], bF[4][2];
            #pragma unroll
            for (int i = 0; i < 4; i++) {
                int r0 = wm + i * 16 + gid;
                aF[i][0] = As[cur][kb + tig][r0];
                aF[i][1] = As[cur][kb + tig][r0 + 8];
                aF[i][2] = As[cur][kb + tig + 4][r0];
                aF[i][3] = As[cur][kb + tig + 4][r0 + 8];
            }
            #pragma unroll
            for (int j = 0; j < 4; j++) {
                int c0 = wn + j * 8 + gid;
                bF[j][0] = Bs[cur][kb + tig][c0];
                bF[j][1] = Bs[cur][kb + tig + 4][c0];
            }
            #pragma unroll
            for (int i = 0; i < 4; i++)
                #pragma unroll
                for (int j = 0; j < 4; j++)
                    mma_tf32(acc[i][j], aF[i], bF[j]);
        }
        if (t + 1 < nT) {
            STS_TILE(1 - cur);
            if (t + 2 < nT) LDG_TILE(k0 + (t + 2) * 16);
        }
        __syncthreads();
    }

    // epilogue
    if (split == 1) {
        float* Cb = C + (long)z * strideC;
        #pragma unroll
        for (int i = 0; i < 4; i++) {
            int row = bm + wm + i * 16 + gid;
            #pragma unroll
            for (int j = 0; j < 4; j++) {
                int col = wn + j * 8 + 2 * tig;
                long i0 = (long)row * ldc + col;
                long i1 = (long)(row + 8) * ldc + col;
                if (accum) {
                    Cb[i0]     += acc[i][j][0];
                    Cb[i0 + 1] += acc[i][j][1];
                    Cb[i1]     += acc[i][j][2];
                    Cb[i1 + 1] += acc[i][j][3];
                } else {
                    Cb[i0]     = acc[i][j][0];
                    Cb[i0 + 1] = acc[i][j][1];
                    Cb[i1]     = acc[i][j][2];
                    Cb[i1 + 1] = acc[i][j][3];
                }
            }
        }
    } else {
        float* Pb = part + ((long)(z * split + ks) * M) * 128;
        #pragma unroll
        for (int i = 0; i < 4; i++) {
            int row = bm + wm + i * 16 + gid;
            #pragma unroll
            for (int j = 0; j < 4; j++) {
                int col = wn + j * 8 + 2 * tig;
                long i0 = (long)row * 128 + col;
                long i1 = (long)(row + 8) * 128 + col;
                Pb[i0]     = acc[i][j][0];
                Pb[i0 + 1] = acc[i][j][1];
                Pb[i1]     = acc[i][j][2];
                Pb[i1 + 1] = acc[i][j][3];
            }
        }
    }
#undef LDG_TILE
#undef STS_TILE
}

// deterministic split-K reduction (float4): C = (accum ? C : 0) + sum_s part
__global__ void reduce_split(const float* __restrict__ part, float* __restrict__ C,
                             long MN, int split, int accum, long total) {
    long i4 = (long)blockIdx.x * blockDim.x + threadIdx.x;
    long total4 = total >> 2;
    if (i4 >= total4) return;
    long MN4 = MN >> 2;
    long zi = i4 / MN4, mn = i4 % MN4;
    const float4* p4 = (const float4*)part;
    float4* c4 = (float4*)C;
    float4 s;
    if (accum) s = c4[i4];
    else { s.x = 0.f; s.y = 0.f; s.z = 0.f; s.w = 0.f; }
    for (int k = 0; k < split; k++) {
        float4 v = p4[(zi * (long)split + k) * MN4 + mn];
        s.x += v.x; s.y += v.y; s.z += v.z; s.w += v.w;
    }
    c4[i4] = s;
}

// ---------------- elementwise copy ----------------
__global__ void copy_kernel(const float* __restrict__ src, float* __restrict__ dst, int n) {
    int i = blockIdx.x * blockDim.x + threadIdx.x;
    if (i < n) dst[i] = src[i];
}

// ---------------- RMSNorm over D for each (b, s) ----------------
__global__ void rmsnorm_kernel(const float* __restrict__ x, const float* __restrict__ w,
                               float* __restrict__ out) {
    int s = blockIdx.x * 32 + threadIdx.x;
    int b = blockIdx.y;
    const float* xb = x + (long)b * DIM * SEQ;
    float* ob = out + (long)b * DIM * SEQ;
    float ss = 0.0f;
    for (int d = threadIdx.y; d < DIM; d += 8) {
        float v = xb[d * SEQ + s];
        ss += v * v;
    }
    __shared__ float red[8][33];
    red[threadIdx.y][threadIdx.x] = ss;
    __syncthreads();
    if (threadIdx.y == 0) {
        float tot = 0.0f;
        #pragma unroll
        for (int i = 0; i < 8; i++) tot += red[i][threadIdx.x];
        red[0][threadIdx.x] = rsqrtf(tot / (float)DIM + EPSV);
    }
    __syncthreads();
    float inv = red[0][threadIdx.x];
    for (int d = threadIdx.y; d < DIM; d += 8) {
        ob[d * SEQ + s] = xb[d * SEQ + s] * inv * w[d];
    }
}

// ---------------- RoPE in-place on (B, H, 128, S) buffer ----------------
__global__ void rope_kernel(float* __restrict__ q, const int* __restrict__ positions, int H) {
    int idx = blockIdx.x * blockDim.x + threadIdx.x;
    int total = NB * H * 64 * SEQ;
    if (idx >= total) return;
    int s = idx % SEQ;
    int i = (idx / SEQ) % 64;
    int h = (idx / (SEQ * 64)) % H;
    int b = idx / (SEQ * 64 * H);
    float pos = (float)positions[b * SEQ + s];
    float inv = powf(10000.0f, -(float)i / 64.0f);
    float sn, cs;
    sincosf(pos * inv, &sn, &cs);
    long base = (((long)b * H + h) * HDN) * SEQ;
    float x1 = q[base + (long)i * SEQ + s];
    float x2 = q[base + (long)(i + 64) * SEQ + s];
    q[base + (long)i * SEQ + s] = x1 * cs - x2 * sn;
    q[base + (long)(i + 64) * SEQ + s] = x2 * cs + x1 * sn;
}

// ---------------- merge k into key scratch: key[b,k,a,d] ----------------
__global__ void update_key(const float* __restrict__ kc, const float* __restrict__ knew,
                           float* __restrict__ keybuf, const int* __restrict__ wptr) {
    int idx = blockIdx.x * blockDim.x + threadIdx.x;
    const int total = NB * HKVN * ALEN * HDN;
    if (idx >= total) return;
    int w = wptr[0];
    int d = idx % HDN;
    int a = (idx / HDN) % ALEN;
    int kh = (idx / (HDN * ALEN)) % HKVN;
    int b = idx / (HDN * ALEN * HKVN);
    float v;
    if (a >= w && a < w + SEQ) {
        v = knew[(((long)b * HKVN + kh) * HDN + d) * SEQ + (a - w)];
    } else {
        v = kc[idx];
    }
    keybuf[idx] = v;
}

// ---------------- merge v into val scratch: val[b,k,d,a] ----------------
__global__ void update_val(const float* __restrict__ vc, const float* __restrict__ vnew,
                           float* __restrict__ valbuf, const int* __restrict__ wptr) {
    int idx = blockIdx.x * blockDim.x + threadIdx.x;
    const int total = NB * HKVN * HDN * ALEN;
    if (idx >= total) return;
    int w = wptr[0];
    int a = idx % ALEN;
    int d = (idx / ALEN) % HDN;
    int kh = (idx / (ALEN * HDN)) % HKVN;
    int b = idx / (ALEN * HDN * HKVN);
    float v;
    if (a >= w && a < w + SEQ) {
        v = vnew[(((long)b * HKVN + kh) * HDN + d) * SEQ + (a - w)];
    } else {
        v = vc[idx];
    }
    valbuf[idx] = v;
}

// ---------------- self-attn softmax over a ----------------
__global__ void sa_softmax(float* __restrict__ sc, const int* __restrict__ wptr, float scale) {
    int s = blockIdx.x * 32 + threadIdx.x;
    int z = blockIdx.y;
    int w = wptr[0];
    float* p = sc + (long)z * ALEN * SEQ;
    __shared__ float red[8][33];

    float mx = -3.0e38f;
    for (int a = threadIdx.y; a < ALEN; a += 8) {
        float v = p[(long)a * SEQ + s] * scale;
        if (a > w + s) v += NEGV;
        p[(long)a * SEQ + s] = v;
        mx = fmaxf(mx, v);
    }
    red[threadIdx.y][threadIdx.x] = mx;
    __syncthreads();
    if (threadIdx.y == 0) {
        float m = red[0][threadIdx.x];
        #pragma unroll
        for (int i = 1; i < 8; i++) m = fmaxf(m, red[i][threadIdx.x]);
        red[0][threadIdx.x] = m;
    }
    __syncthreads();
    mx = red[0][threadIdx.x];
    __syncthreads();

    float sum = 0.0f;
    for (int a = threadIdx.y; a < ALEN; a += 8) {
        float e = expf(p[(long)a * SEQ + s] - mx);
        p[(long)a * SEQ + s] = e;
        sum += e;
    }
    red[threadIdx.y][threadIdx.x] = sum;
    __syncthreads();
    if (threadIdx.y == 0) {
        float t = red[0][threadIdx.x];
        #pragma unroll
        for (int i = 1; i < 8; i++) t += red[i][threadIdx.x];
        red[0][threadIdx.x] = 1.0f / t;
    }
    __syncthreads();
    float rinv = red[0][threadIdx.x];
    for (int a = threadIdx.y; a < ALEN; a += 8) {
        p[(long)a * SEQ + s] *= rinv;
    }
}

// ---------------- cross-attn softmax over t ----------------
__global__ void ca_softmax(float* __restrict__ sc, const int* __restrict__ enc, float scale) {
    int s = blockIdx.x * 32 + threadIdx.x;
    int z = blockIdx.y;
    int b = z / HCN;
    int len = enc[b];
    float* p = sc + (long)z * TLEN * SEQ;
    __shared__ float red[8][33];

    float mx = -3.0e38f;
    for (int t = threadIdx.y; t < TLEN; t += 8) {
        float v = p[(long)t * SEQ + s] * scale;
        if (t >= len) v += NEGV;
        p[(long)t * SEQ + s] = v;
        mx = fmaxf(mx, v);
    }
    red[threadIdx.y][threadIdx.x] = mx;
    __syncthreads();
    if (threadIdx.y == 0) {
        float m = red[0][threadIdx.x];
        #pragma unroll
        for (int i = 1; i < 8; i++) m = fmaxf(m, red[i][threadIdx.x]);
        red[0][threadIdx.x] = m;
    }
    __syncthreads();
    mx = red[0][threadIdx.x];
    __syncthreads();

    float sum = 0.0f;
    for (int t = threadIdx.y; t < TLEN; t += 8) {
        float e = expf(p[(long)t * SEQ + s] - mx);
        p[(long)t * SEQ + s] = e;
        sum += e;
    }
    red[threadIdx.y][threadIdx.x] = sum;
    __syncthreads();
    if (threadIdx.y == 0) {
        float t = red[0][threadIdx.x];
        #pragma unroll
        for (int i = 1; i < 8; i++) t += red[i][threadIdx.x];
        red[0][threadIdx.x] = 1.0f / t;
    }
    __syncthreads();
    float rinv = red[0][threadIdx.x];
    for (int t = threadIdx.y; t < TLEN; t += 8) {
        p[(long)t * SEQ + s] *= rinv;
    }
}

// ---------------- silu(gate) * up, in place into gate ----------------
__global__ void silu_mul(float* __restrict__ gate, const float* __restrict__ up, int n) {
    int i = blockIdx.x * blockDim.x + threadIdx.x;
    if (i < n) {
        float g = gate[i];
        gate[i] = (g / (1.0f + expf(-g))) * up[i];
    }
}

// ---------------- host orchestration ----------------
extern "C" void kernel_launch(void* const* d_in, const int* in_sizes, int n_in,
                              void* d_out, int out_size) {
    const float* x_in     = (const float*)d_in[0];
    const int*   positions= (const int*)d_in[1];
    const int*   kvw      = (const int*)d_in[2];
    const int*   enc_len  = (const int*)d_in[4];
    const float* q_w      = (const float*)d_in[5];
    const float* k_w      = (const float*)d_in[6];
    const float* v_w      = (const float*)d_in[7];
    const float* o_w      = (const float*)d_in[8];
    const float* cq_w     = (const float*)d_in[9];
    const float* co_w     = (const float*)d_in[10];
    const float* sa_norm  = (const float*)d_in[11];
    const float* ca_norm  = (const float*)d_in[12];
    const float* mlp_norm = (const float*)d_in[13];
    const float* fin_norm = (const float*)d_in[14];
    const float* wg_w     = (const float*)d_in[15];
    const float* wu_w     = (const float*)d_in[16];
    const float* wd_w     = (const float*)d_in[17];
    const float* k_cache  = (const float*)d_in[18];
    const float* v_cache  = (const float*)d_in[19];
    const float* ck_cache = (const float*)d_in[20];
    const float* cv_cache = (const float*)d_in[21];

    float *px, *ph, *pq, *pk, *pv, *pkey, *pval, *psc, *pattn, *pcsc, *pgate, *pup, *ppart;
    cudaGetSymbolAddress((void**)&px,    g_x);
    cudaGetSymbolAddress((void**)&ph,    g_h);
    cudaGetSymbolAddress((void**)&pq,    g_q);
    cudaGetSymbolAddress((void**)&pk,    g_k);
    cudaGetSymbolAddress((void**)&pv,    g_v);
    cudaGetSymbolAddress((void**)&pkey,  g_key);
    cudaGetSymbolAddress((void**)&pval,  g_val);
    cudaGetSymbolAddress((void**)&psc,   g_scores);
    cudaGetSymbolAddress((void**)&pattn, g_attn);
    cudaGetSymbolAddress((void**)&pcsc,  g_cscores);
    cudaGetSymbolAddress((void**)&pgate, g_gate);
    cudaGetSymbolAddress((void**)&pup,   g_up);
    cudaGetSymbolAddress((void**)&ppart, g_part);

    const float scale  = 0.08838834764831845f;  // 1/sqrt(128)
    dim3 blk328(32, 8);

    {
        int n = NB * DIM * SEQ;
        copy_kernel<<<(n + 255) / 256, 256>>>(x_in, px, n);
    }

    for (int l = 0; l < NLAYER; l++) {
        long wOffD2   = (long)l * DIM * DIM;
        long wOffKV   = (long)l * DIM * (HKVN * HDN);
        long wOffFF   = (long)l * DIM * FFN;
        long wOffFFd  = (long)l * FFN * DIM;
        long cOffK    = (long)l * NB * HCN * TLEN * HDCN;
        long cOffV    = (long)l * NB * HCN * HDCN * TLEN;

        // ---- self attention ----
        rmsnorm_kernel<<<dim3(SEQ / 32, NB), blk328>>>(px, sa_norm + (long)l * DIM, ph);

        // q: TN, K=2048, M=2048, split=16 -> 512 CTAs
        gemm_mma<<<dim3(16, 16, NB), 256>>>(q_w + wOffD2, ph, pq,
            DIM, 2048, 2048, SEQ, SEQ, 0, 1, (long)DIM * SEQ, 0, 0, 1, 16, ppart);
        reduce_split<<<(NB * 2048 * 128 / 4 + 255) / 256, 256>>>(ppart, pq, 2048L * 128, 16, 0, (long)NB * 2048 * 128);
        // k: TN, M=512, split=32 -> 256 CTAs
        gemm_mma<<<dim3(4, 32, NB), 256>>>(k_w + wOffKV, ph, pk,
            DIM, 512, 512, SEQ, SEQ, 0, 1, (long)DIM * SEQ, 0, 0, 1, 32, ppart);
        reduce_split<<<(NB * 512 * 128 / 4 + 255) / 256, 256>>>(ppart, pk, 512L * 128, 32, 0, (long)NB * 512 * 128);
        // v
        gemm_mma<<<dim3(4, 32, NB), 256>>>(v_w + wOffKV, ph, pv,
            DIM, 512, 512, SEQ, SEQ, 0, 1, (long)DIM * SEQ, 0, 0, 1, 32, ppart);
        reduce_split<<<(NB * 512 * 128 / 4 + 255) / 256, 256>>>(ppart, pv, 512L * 128, 32, 0, (long)NB * 512 * 128);

        {
            int nq = NB * HQN * 64 * SEQ;
            rope_kernel<<<(nq + 255) / 256, 256>>>(pq, positions, HQN);
            int nk = NB * HKVN * 64 * SEQ;
            rope_kernel<<<(nk + 255) / 256, 256>>>(pk, positions, HKVN);
        }
        {
            int n = NB * HKVN * ALEN * HDN;
            update_key<<<(n + 255) / 256, 256>>>(
                k_cache + (long)l * NB * HKVN * ALEN * HDN, pk, pkey, kvw);
            update_val<<<(n + 255) / 256, 256>>>(
                v_cache + (long)l * NB * HKVN * HDN * ALEN, pv, pval, kvw);
        }

        // scores: NN, K=128, M=1536, z=32 -> 384 CTAs, split=1
        gemm_mma<<<dim3(12, 1, NB * HQN), 256>>>(pkey, pq, psc,
            HDN, ALEN, HDN, SEQ, SEQ, (long)ALEN * HDN, GRP, (long)HDN * SEQ, (long)ALEN * SEQ, 0, 0, 1, ppart);

        sa_softmax<<<dim3(SEQ / 32, NB * HQN), blk328>>>(psc, kvw, scale);

        // attn = val @ probs: NN, K=1536, M=128, z=32, split=8 -> 256 CTAs
        gemm_mma<<<dim3(1, 8, NB * HQN), 256>>>(pval, psc, pattn,
            ALEN, HDN, ALEN, SEQ, SEQ, (long)HDN * ALEN, GRP, (long)ALEN * SEQ, 0, 0, 0, 8, ppart);
        reduce_split<<<(32 * 128 * 128 / 4 + 255) / 256, 256>>>(ppart, pattn, 128L * 128, 8, 0, 32L * 128 * 128);

        // o: TN, K=2048, M=2048, split=16, accumulate into x via reduce
        gemm_mma<<<dim3(16, 16, NB), 256>>>(o_w + wOffD2, pattn, px,
            HQN * HDN, DIM, DIM, SEQ, SEQ, 0, 1, (long)HQN * HDN * SEQ, 0, 0, 1, 16, ppart);
        reduce_split<<<(NB * 2048 * 128 / 4 + 255) / 256, 256>>>(ppart, px, 2048L * 128, 16, 1, (long)NB * 2048 * 128);

        // ---- cross attention ----
        rmsnorm_kernel<<<dim3(SEQ / 32, NB), blk328>>>(px, ca_norm + (long)l * DIM, ph);

        gemm_mma<<<dim3(16, 16, NB), 256>>>(cq_w + wOffD2, ph, pq,
            DIM, 2048, 2048, SEQ, SEQ, 0, 1, (long)DIM * SEQ, 0, 0, 1, 16, ppart);
        reduce_split<<<(NB * 2048 * 128 / 4 + 255) / 256, 256>>>(ppart, pq, 2048L * 128, 16, 0, (long)NB * 2048 * 128);
        {
            int nq = NB * HCN * 64 * SEQ;
            rope_kernel<<<(nq + 255) / 256, 256>>>(pq, positions, HCN);
        }

        // cscores: NN, K=128, M=512, z=32 -> 128 CTAs, split=1
        gemm_mma<<<dim3(4, 1, NB * HCN), 256>>>(ck_cache + cOffK, pq, pcsc,
            HDCN, TLEN, HDCN, SEQ, SEQ, (long)TLEN * HDCN, 1, (long)HDCN * SEQ, (long)TLEN * SEQ, 0, 0, 1, ppart);

        ca_softmax<<<dim3(SEQ / 32, NB * HCN), blk328>>>(pcsc, enc_len, scale);

        // cattn: NN, K=512, M=128, z=32, split=8 -> 256 CTAs
        gemm_mma<<<dim3(1, 8, NB * HCN), 256>>>(cv_cache + cOffV, pcsc, pattn,
            TLEN, HDCN, TLEN, SEQ, SEQ, (long)HDCN * TLEN, 1, (long)TLEN * SEQ, 0, 0, 0, 8, ppart);
        reduce_split<<<(32 * 128 * 128 / 4 + 255) / 256, 256>>>(ppart, pattn, 128L * 128, 8, 0, 32L * 128 * 128);

        // co: accumulate into x
        gemm_mma<<<dim3(16, 16, NB), 256>>>(co_w + wOffD2, pattn, px,
            HCN * HDCN, DIM, DIM, SEQ, SEQ, 0, 1, (long)HCN * HDCN * SEQ, 0, 0, 1, 16, ppart);
        reduce_split<<<(NB * 2048 * 128 / 4 + 255) / 256, 256>>>(ppart, px, 2048L * 128, 16, 1, (long)NB * 2048 * 128);

        // ---- MLP ----
        rmsnorm_kernel<<<dim3(SEQ / 32, NB), blk328>>>(px, mlp_norm + (long)l * DIM, ph);

        // gate/up: M=8192, split=2 -> 256 CTAs each
        gemm_mma<<<dim3(64, 2, NB), 256>>>(wg_w + wOffFF, ph, pgate,
            DIM, FFN, FFN, SEQ, SEQ, 0, 1, (long)DIM * SEQ, 0, 0, 1, 2, ppart);
        reduce_split<<<(NB * FFN * 128 / 4 + 255) / 256, 256>>>(ppart, pgate, (long)FFN * 128, 2, 0, (long)NB * FFN * 128);
        gemm_mma<<<dim3(64, 2, NB), 256>>>(wu_w + wOffFF, ph, pup,
            DIM, FFN, FFN, SEQ, SEQ, 0, 1, (long)DIM * SEQ, 0, 0, 1, 2, ppart);
        reduce_split<<<(NB * FFN * 128 / 4 + 255) / 256, 256>>>(ppart, pup, (long)FFN * 128, 2, 0, (long)NB * FFN * 128);
        {
            int n = NB * FFN * SEQ;
            silu_mul<<<(n + 255) / 256, 256>>>(pgate, pup, n);
        }
        // down: TN, K=8192, M=2048, split=16 -> 512 CTAs, accumulate into x
        gemm_mma<<<dim3(16, 16, NB), 256>>>(wd_w + wOffFFd, pgate, px,
            FFN, DIM, DIM, SEQ, SEQ, 0, 1, (long)FFN * SEQ, 0, 0, 1, 16, ppart);
        reduce_split<<<(NB * 2048 * 128 / 4 + 255) / 256, 256>>>(ppart, px, 2048L * 128, 16, 1, (long)NB * 2048 * 128);
    }

    rmsnorm_kernel<<<dim3(SEQ / 32, NB), blk328>>>(px, fin_norm, (float*)d_out);
}